// round 1
// baseline (speedup 1.0000x reference)
#include <cuda_runtime.h>
#include <cuda_bf16.h>
#include <float.h>

#define N_NODES 20000
#define N_EDGES 320000
#define ET      340000
#define IN_CH   512
#define HID     128
#define HEADS   4
#define F1      512
#define OUT_CH  30
#define NEG_SLOPE 0.2f

__device__ float g_h1[N_NODES * F1];
__device__ float g_agg1[N_NODES * F1];
__device__ float g_alS1[N_NODES * HEADS];
__device__ float g_alD1[N_NODES * HEADS];
__device__ float g_emax1[N_NODES * HEADS];
__device__ float g_den1[N_NODES * HEADS];
__device__ float g_e1[ET * HEADS];
__device__ float g_zpre[N_NODES * OUT_CH];
__device__ float g_alS2[N_NODES];
__device__ float g_alD2[N_NODES];
__device__ float g_emax2[N_NODES];
__device__ float g_den2[N_NODES];
__device__ float g_e2[ET];
__device__ float g_agg2[N_NODES * OUT_CH];
__device__ float g_zf[N_NODES * OUT_CH];

__device__ __forceinline__ void atomicMaxF(float* addr, float val) {
    int* ai = (int*)addr;
    int old = *ai;
    while (__int_as_float(old) < val) {
        int assumed = old;
        old = atomicCAS(ai, assumed, __float_as_int(val));
        if (old == assumed) break;
    }
}

__device__ __forceinline__ void edge_endpoints(int e, const int* __restrict__ ei,
                                               int& src, int& dst) {
    if (e < N_EDGES) { src = ei[e]; dst = ei[N_EDGES + e]; }
    else { src = e - N_EDGES; dst = src; }
}

__global__ void k_init() {
    int i = blockIdx.x * blockDim.x + threadIdx.x;
    if (i < N_NODES * F1) g_agg1[i] = 0.f;
    if (i < N_NODES * HEADS) { g_emax1[i] = -FLT_MAX; g_den1[i] = 0.f; }
    if (i < N_NODES) { g_emax2[i] = -FLT_MAX; g_den2[i] = 0.f; }
    if (i < N_NODES * OUT_CH) g_agg2[i] = 0.f;
}

#define BM 128
#define BN 128
#define BK 16
__global__ __launch_bounds__(256, 1)
void k_sgemm(const float* __restrict__ A, const float* __restrict__ B,
             float* __restrict__ C, int M, int N, int K) {
    __shared__ float As[BK][BM];
    __shared__ float Bs[BK][BN];
    const int tid = threadIdx.x;
    const int tr = tid >> 4;
    const int tc = tid & 15;
    const int rowBase = blockIdx.y * BM;
    const int colBase = blockIdx.x * BN;

    float acc[8][8];
    #pragma unroll
    for (int i = 0; i < 8; i++)
        #pragma unroll
        for (int j = 0; j < 8; j++) acc[i][j] = 0.f;

    for (int k0 = 0; k0 < K; k0 += BK) {
        #pragma unroll
        for (int t = 0; t < 2; t++) {
            int i = tid * 2 + t;
            int r = i >> 2;
            int c = (i & 3) * 4;
            int gr = rowBase + r;
            float4 v = make_float4(0.f, 0.f, 0.f, 0.f);
            if (gr < M) v = *(const float4*)&A[(size_t)gr * K + k0 + c];
            As[c + 0][r] = v.x; As[c + 1][r] = v.y; As[c + 2][r] = v.z; As[c + 3][r] = v.w;
        }
        #pragma unroll
        for (int t = 0; t < 2; t++) {
            int i = tid * 2 + t;
            int r = i >> 5;
            int c = (i & 31) * 4;
            *(float4*)&Bs[r][c] = *(const float4*)&B[(size_t)(k0 + r) * N + colBase + c];
        }
        __syncthreads();
        #pragma unroll
        for (int k = 0; k < BK; k++) {
            float a[8], b[8];
            #pragma unroll
            for (int i = 0; i < 8; i++) a[i] = As[k][tr * 8 + i];
            #pragma unroll
            for (int j = 0; j < 8; j++) b[j] = Bs[k][tc * 8 + j];
            #pragma unroll
            for (int i = 0; i < 8; i++)
                #pragma unroll
                for (int j = 0; j < 8; j++) acc[i][j] = fmaf(a[i], b[j], acc[i][j]);
        }
        __syncthreads();
    }
    #pragma unroll
    for (int i = 0; i < 8; i++) {
        int gr = rowBase + tr * 8 + i;
        if (gr >= M) continue;
        #pragma unroll
        for (int j = 0; j < 8; j += 4) {
            float4 v = make_float4(acc[i][j], acc[i][j+1], acc[i][j+2], acc[i][j+3]);
            *(float4*)&C[(size_t)gr * N + colBase + tc * 8 + j] = v;
        }
    }
}

__global__ void k_logits1(const float* __restrict__ aS, const float* __restrict__ aD) {
    int n = blockIdx.x;
    int w = threadIdx.x >> 5, lane = threadIdx.x & 31;
    const float* hr = g_h1 + (size_t)n * F1 + w * HID;
    const float* av = aS + w * HID;
    const float* dv = aD + w * HID;
    float s = 0.f, d = 0.f;
    #pragma unroll
    for (int i = 0; i < 4; i++) {
        float hv = hr[lane + i * 32];
        s = fmaf(hv, av[lane + i * 32], s);
        d = fmaf(hv, dv[lane + i * 32], d);
    }
    #pragma unroll
    for (int o = 16; o > 0; o >>= 1) {
        s += __shfl_down_sync(0xffffffffu, s, o);
        d += __shfl_down_sync(0xffffffffu, d, o);
    }
    if (lane == 0) { g_alS1[n * HEADS + w] = s; g_alD1[n * HEADS + w] = d; }
}

__global__ void k_edge1_max(const int* __restrict__ ei) {
    int e = blockIdx.x * blockDim.x + threadIdx.x;
    if (e >= ET) return;
    int src, dst; edge_endpoints(e, ei, src, dst);
    float4 s = *(const float4*)&g_alS1[src * HEADS];
    float4 d = *(const float4*)&g_alD1[dst * HEADS];
    float v[4] = { s.x + d.x, s.y + d.y, s.z + d.z, s.w + d.w };
    #pragma unroll
    for (int h = 0; h < 4; h++) {
        float lv = v[h] > 0.f ? v[h] : NEG_SLOPE * v[h];
        g_e1[e * 4 + h] = lv;
        atomicMaxF(&g_emax1[dst * 4 + h], lv);
    }
}

__global__ void k_edge1_exp(const int* __restrict__ ei) {
    int e = blockIdx.x * blockDim.x + threadIdx.x;
    if (e >= ET) return;
    int src, dst; edge_endpoints(e, ei, src, dst);
    (void)src;
    #pragma unroll
    for (int h = 0; h < 4; h++) {
        float p = __expf(g_e1[e * 4 + h] - g_emax1[dst * 4 + h]);
        g_e1[e * 4 + h] = p;
        atomicAdd(&g_den1[dst * 4 + h], p);
    }
}

__global__ void k_edge1_agg(const int* __restrict__ ei) {
    int gw = (blockIdx.x * blockDim.x + threadIdx.x) >> 5;
    int lane = threadIdx.x & 31;
    if (gw >= ET) return;
    int src, dst; edge_endpoints(gw, ei, src, dst);
    #pragma unroll
    for (int h = 0; h < 4; h++) {
        float alpha = g_e1[gw * 4 + h] / g_den1[dst * 4 + h];
        float4 v = *(const float4*)&g_h1[(size_t)src * F1 + h * HID + lane * 4];
        v.x *= alpha; v.y *= alpha; v.z *= alpha; v.w *= alpha;
        atomicAdd((float4*)&g_agg1[(size_t)dst * F1 + h * HID + lane * 4], v);
    }
}

__global__ void k_elu(const float* __restrict__ b1) {
    int i = blockIdx.x * blockDim.x + threadIdx.x;
    if (i >= N_NODES * F1) return;
    float v = g_agg1[i] + b1[i & (F1 - 1)];
    g_agg1[i] = v > 0.f ? v : expm1f(v);
}

__global__ void k_gemm2(const float* __restrict__ W2,
                        const float* __restrict__ aS2, const float* __restrict__ aD2) {
    __shared__ float sh[F1];
    __shared__ float sz[32];
    int n = blockIdx.x, t = threadIdx.x;
    *(float4*)&sh[t * 4] = *(const float4*)&g_agg1[(size_t)n * F1 + t * 4];
    __syncthreads();
    if (t < OUT_CH) {
        float acc = 0.f;
        #pragma unroll 8
        for (int k = 0; k < F1; k++) acc = fmaf(sh[k], W2[k * OUT_CH + t], acc);
        sz[t] = acc;
        g_zpre[n * OUT_CH + t] = acc;
    }
    __syncthreads();
    if (t < 32) {
        float ps = (t < OUT_CH) ? sz[t] * aS2[t] : 0.f;
        float pd = (t < OUT_CH) ? sz[t] * aD2[t] : 0.f;
        #pragma unroll
        for (int o = 16; o > 0; o >>= 1) {
            ps += __shfl_down_sync(0xffffffffu, ps, o);
            pd += __shfl_down_sync(0xffffffffu, pd, o);
        }
        if (t == 0) { g_alS2[n] = ps; g_alD2[n] = pd; }
    }
}

__global__ void k_edge2_max(const int* __restrict__ ei) {
    int e = blockIdx.x * blockDim.x + threadIdx.x;
    if (e >= ET) return;
    int src, dst; edge_endpoints(e, ei, src, dst);
    float v = g_alS2[src] + g_alD2[dst];
    v = v > 0.f ? v : NEG_SLOPE * v;
    g_e2[e] = v;
    atomicMaxF(&g_emax2[dst], v);
}

__global__ void k_edge2_exp(const int* __restrict__ ei) {
    int e = blockIdx.x * blockDim.x + threadIdx.x;
    if (e >= ET) return;
    int src, dst; edge_endpoints(e, ei, src, dst);
    (void)src;
    float p = __expf(g_e2[e] - g_emax2[dst]);
    g_e2[e] = p;
    atomicAdd(&g_den2[dst], p);
}

__global__ void k_edge2_agg(const int* __restrict__ ei) {
    int gw = (blockIdx.x * blockDim.x + threadIdx.x) >> 5;
    int lane = threadIdx.x & 31;
    if (gw >= ET) return;
    int src, dst; edge_endpoints(gw, ei, src, dst);
    float alpha = g_e2[gw] / g_den2[dst];
    if (lane < OUT_CH)
        atomicAdd(&g_agg2[dst * OUT_CH + lane], alpha * g_zpre[src * OUT_CH + lane]);
}

__global__ void k_zfinal(const float* __restrict__ b2, float* __restrict__ outZ) {
    int i = blockIdx.x * blockDim.x + threadIdx.x;
    if (i >= N_NODES * OUT_CH) return;
    float v = g_agg2[i] + b2[i % OUT_CH];
    g_zf[i] = v;
    outZ[i] = v;
}

__global__ void k_decoder(const float* __restrict__ Wd, const float* __restrict__ bd,
                          float* __restrict__ out) {
    __shared__ float sz[OUT_CH];
    int n = blockIdx.x, t = threadIdx.x;
    if (t < OUT_CH) sz[t] = g_zf[n * OUT_CH + t];
    __syncthreads();
    float4 acc = *(const float4*)&bd[t * 4];
    #pragma unroll
    for (int k = 0; k < OUT_CH; k++) {
        float zv = sz[k];
        float4 w = *(const float4*)&Wd[k * IN_CH + t * 4];
        acc.x = fmaf(zv, w.x, acc.x);
        acc.y = fmaf(zv, w.y, acc.y);
        acc.z = fmaf(zv, w.z, acc.z);
        acc.w = fmaf(zv, w.w, acc.w);
    }
    *(float4*)&out[(size_t)n * IN_CH + t * 4] = acc;
}

extern "C" void kernel_launch(void* const* d_in, const int* in_sizes, int n_in,
                              void* d_out, int out_size) {
    const float* x   = (const float*)d_in[0];
    const int*   ei  = (const int*)d_in[1];
    const float* W1  = (const float*)d_in[2];
    const float* aS1 = (const float*)d_in[3];
    const float* aD1 = (const float*)d_in[4];
    const float* b1  = (const float*)d_in[5];
    const float* W2  = (const float*)d_in[6];
    const float* aS2 = (const float*)d_in[7];
    const float* aD2 = (const float*)d_in[8];
    const float* b2  = (const float*)d_in[9];
    const float* Wd  = (const float*)d_in[10];
    const float* bd  = (const float*)d_in[11];
    (void)in_sizes; (void)n_in; (void)out_size;

    float* out  = (float*)d_out;
    float* outZ = out + (size_t)N_NODES * IN_CH;

    k_init<<<(N_NODES * F1 + 255) / 256, 256>>>();

    {
        float* C; cudaGetSymbolAddress((void**)&C, g_h1);
        dim3 grid(F1 / BN, (N_NODES + BM - 1) / BM);
        k_sgemm<<<grid, 256>>>(x, W1, C, N_NODES, F1, IN_CH);
    }

    k_logits1<<<N_NODES, 128>>>(aS1, aD1);

    int eb = (ET + 255) / 256;
    k_edge1_max<<<eb, 256>>>(ei);
    k_edge1_exp<<<eb, 256>>>(ei);
    k_edge1_agg<<<(ET * 32 + 255) / 256, 256>>>(ei);

    k_elu<<<(N_NODES * F1 + 255) / 256, 256>>>(b1);

    k_gemm2<<<N_NODES, 128>>>(W2, aS2, aD2);

    k_edge2_max<<<eb, 256>>>(ei);
    k_edge2_exp<<<eb, 256>>>(ei);
    k_edge2_agg<<<(ET * 32 + 255) / 256, 256>>>(ei);

    k_zfinal<<<(N_NODES * OUT_CH + 255) / 256, 256>>>(b2, outZ);
    k_decoder<<<N_NODES, 128>>>(Wd, bd, out);
}

// round 2
// speedup vs baseline: 1.0788x; 1.0788x over previous
#include <cuda_runtime.h>
#include <cuda_bf16.h>
#include <float.h>

#define N_NODES 20000
#define N_EDGES 320000
#define ET      340000
#define IN_CH   512
#define HID     128
#define HEADS   4
#define F1      512
#define OUT_CH  30
#define NEG_SLOPE 0.2f

__device__ float g_h1[N_NODES * F1];
__device__ float g_agg1[N_NODES * F1];
__device__ float g_alS1[N_NODES * HEADS];
__device__ float g_alD1[N_NODES * HEADS];
__device__ float g_den1[N_NODES * HEADS];
__device__ float g_e1[ET * HEADS];
__device__ float g_zpre[N_NODES * OUT_CH];
__device__ float g_alS2[N_NODES];
__device__ float g_alD2[N_NODES];
__device__ float g_den2[N_NODES];
__device__ float g_e2[ET];
__device__ float g_agg2[N_NODES * OUT_CH];

__device__ __forceinline__ void edge_endpoints(int e, const int* __restrict__ ei,
                                               int& src, int& dst) {
    if (e < N_EDGES) { src = ei[e]; dst = ei[N_EDGES + e]; }
    else { src = e - N_EDGES; dst = src; }
}

// ---- packed f32x2 helpers (Blackwell FFMA2 path) ----
__device__ __forceinline__ unsigned long long pk2(float lo, float hi) {
    unsigned long long r;
    asm("mov.b64 %0, {%1, %2};" : "=l"(r) : "f"(lo), "f"(hi));
    return r;
}
__device__ __forceinline__ void upk2(unsigned long long v, float& lo, float& hi) {
    asm("mov.b64 {%0, %1}, %2;" : "=f"(lo), "=f"(hi) : "l"(v));
}
__device__ __forceinline__ void ffma2(unsigned long long& acc,
                                      unsigned long long a, unsigned long long b) {
    asm("fma.rn.f32x2 %0, %1, %2, %0;" : "+l"(acc) : "l"(a), "l"(b));
}

__global__ void k_init() {
    int i = blockIdx.x * blockDim.x + threadIdx.x;
    if (i < N_NODES * F1) g_agg1[i] = 0.f;
    if (i < N_NODES * HEADS) g_den1[i] = 0.f;
    if (i < N_NODES) g_den2[i] = 0.f;
    if (i < N_NODES * OUT_CH) g_agg2[i] = 0.f;
}

// ---------------- GEMM: C[M,N] = A[M,K] @ B[K,N], f32x2 packed FMA ----------------
#define BM 128
#define BN 128
#define BK 16
__global__ __launch_bounds__(256, 2)
void k_sgemm(const float* __restrict__ A, const float* __restrict__ B,
             float* __restrict__ C, int M, int N, int K) {
    __shared__ float As[BK][BM];
    __shared__ float Bs[BK][BN];
    const int tid = threadIdx.x;
    const int tr = tid >> 4;       // 0..15 (row group)
    const int tc = tid & 15;       // 0..15 (col group)
    const int rowBase = blockIdx.y * BM;
    const int colBase = blockIdx.x * BN;

    // acc2[i2][j]: rows (tr*8 + 2*i2, +1) x col (tc*8 + j), packed pair along rows
    unsigned long long acc2[4][8];
    #pragma unroll
    for (int i = 0; i < 4; i++)
        #pragma unroll
        for (int j = 0; j < 8; j++) acc2[i][j] = 0ull;

    for (int k0 = 0; k0 < K; k0 += BK) {
        #pragma unroll
        for (int t = 0; t < 2; t++) {
            int i = tid * 2 + t;
            int r = i >> 2;
            int c = (i & 3) * 4;
            int gr = rowBase + r;
            float4 v = make_float4(0.f, 0.f, 0.f, 0.f);
            if (gr < M) v = *(const float4*)&A[(size_t)gr * K + k0 + c];
            As[c + 0][r] = v.x; As[c + 1][r] = v.y; As[c + 2][r] = v.z; As[c + 3][r] = v.w;
        }
        #pragma unroll
        for (int t = 0; t < 2; t++) {
            int i = tid * 2 + t;
            int r = i >> 5;
            int c = (i & 31) * 4;
            *(float4*)&Bs[r][c] = *(const float4*)&B[(size_t)(k0 + r) * N + colBase + c];
        }
        __syncthreads();
        #pragma unroll
        for (int k = 0; k < BK; k++) {
            float a[8], b[8];
            #pragma unroll
            for (int i = 0; i < 8; i += 4)
                *(float4*)&a[i] = *(const float4*)&As[k][tr * 8 + i];
            #pragma unroll
            for (int j = 0; j < 8; j += 4)
                *(float4*)&b[j] = *(const float4*)&Bs[k][tc * 8 + j];
            unsigned long long ap[4], bp[8];
            #pragma unroll
            for (int i = 0; i < 4; i++) ap[i] = pk2(a[2 * i], a[2 * i + 1]);
            #pragma unroll
            for (int j = 0; j < 8; j++) bp[j] = pk2(b[j], b[j]);
            #pragma unroll
            for (int i = 0; i < 4; i++)
                #pragma unroll
                for (int j = 0; j < 8; j++) ffma2(acc2[i][j], ap[i], bp[j]);
        }
        __syncthreads();
    }

    #pragma unroll
    for (int i2 = 0; i2 < 4; i2++) {
        float r0[8], r1[8];
        #pragma unroll
        for (int j = 0; j < 8; j++) upk2(acc2[i2][j], r0[j], r1[j]);
        int gr0 = rowBase + tr * 8 + 2 * i2;
        int gr1 = gr0 + 1;
        if (gr0 < M) {
            *(float4*)&C[(size_t)gr0 * N + colBase + tc * 8 + 0] = *(float4*)&r0[0];
            *(float4*)&C[(size_t)gr0 * N + colBase + tc * 8 + 4] = *(float4*)&r0[4];
        }
        if (gr1 < M) {
            *(float4*)&C[(size_t)gr1 * N + colBase + tc * 8 + 0] = *(float4*)&r1[0];
            *(float4*)&C[(size_t)gr1 * N + colBase + tc * 8 + 4] = *(float4*)&r1[4];
        }
    }
}

// ---------------- layer 1 attention logits per node ----------------
__global__ void k_logits1(const float* __restrict__ aS, const float* __restrict__ aD) {
    int n = blockIdx.x;
    int w = threadIdx.x >> 5, lane = threadIdx.x & 31;
    const float* hr = g_h1 + (size_t)n * F1 + w * HID;
    const float* av = aS + w * HID;
    const float* dv = aD + w * HID;
    float s = 0.f, d = 0.f;
    #pragma unroll
    for (int i = 0; i < 4; i++) {
        float hv = hr[lane + i * 32];
        s = fmaf(hv, av[lane + i * 32], s);
        d = fmaf(hv, dv[lane + i * 32], d);
    }
    #pragma unroll
    for (int o = 16; o > 0; o >>= 1) {
        s += __shfl_down_sync(0xffffffffu, s, o);
        d += __shfl_down_sync(0xffffffffu, d, o);
    }
    if (lane == 0) { g_alS1[n * HEADS + w] = s; g_alD1[n * HEADS + w] = d; }
}

// ---------------- layer 1: p = exp(leakyrelu(logit)); den += p ----------------
__global__ void k_edge1_p(const int* __restrict__ ei) {
    int e = blockIdx.x * blockDim.x + threadIdx.x;
    if (e >= ET) return;
    int src, dst; edge_endpoints(e, ei, src, dst);
    float4 s = *(const float4*)&g_alS1[src * HEADS];
    float4 d = *(const float4*)&g_alD1[dst * HEADS];
    float v[4] = { s.x + d.x, s.y + d.y, s.z + d.z, s.w + d.w };
    float p[4];
    #pragma unroll
    for (int h = 0; h < 4; h++) {
        float lv = v[h] > 0.f ? v[h] : NEG_SLOPE * v[h];
        p[h] = __expf(lv);
        atomicAdd(&g_den1[dst * 4 + h], p[h]);
    }
    *(float4*)&g_e1[e * 4] = make_float4(p[0], p[1], p[2], p[3]);
}

// warp per edge: agg1[dst] += alpha_h * h1[src]  (float4 atomics)
__global__ void k_edge1_agg(const int* __restrict__ ei) {
    int gw = (blockIdx.x * blockDim.x + threadIdx.x) >> 5;
    int lane = threadIdx.x & 31;
    if (gw >= ET) return;
    int src, dst; edge_endpoints(gw, ei, src, dst);
    float4 pv = *(const float4*)&g_e1[gw * 4];
    float4 dv = *(const float4*)&g_den1[dst * 4];
    float alpha[4] = { pv.x / dv.x, pv.y / dv.y, pv.z / dv.z, pv.w / dv.w };
    #pragma unroll
    for (int h = 0; h < 4; h++) {
        float4 v = *(const float4*)&g_h1[(size_t)src * F1 + h * HID + lane * 4];
        v.x *= alpha[h]; v.y *= alpha[h]; v.z *= alpha[h]; v.w *= alpha[h];
        atomicAdd((float4*)&g_agg1[(size_t)dst * F1 + h * HID + lane * 4], v);
    }
}

// ---------------- bias + ELU (in place on g_agg1) ----------------
__global__ void k_elu(const float* __restrict__ b1) {
    int i = blockIdx.x * blockDim.x + threadIdx.x;
    if (i >= N_NODES * F1) return;
    float v = g_agg1[i] + b1[i & (F1 - 1)];
    g_agg1[i] = v > 0.f ? v : expm1f(v);
}

// ---------------- layer 2: z_pre = h2 @ W2, plus logits ----------------
__global__ void k_gemm2(const float* __restrict__ W2,
                        const float* __restrict__ aS2, const float* __restrict__ aD2) {
    __shared__ float sh[F1];
    __shared__ float sz[32];
    int n = blockIdx.x, t = threadIdx.x;
    *(float4*)&sh[t * 4] = *(const float4*)&g_agg1[(size_t)n * F1 + t * 4];
    __syncthreads();
    if (t < OUT_CH) {
        float acc = 0.f;
        #pragma unroll 8
        for (int k = 0; k < F1; k++) acc = fmaf(sh[k], W2[k * OUT_CH + t], acc);
        sz[t] = acc;
        g_zpre[n * OUT_CH + t] = acc;
    }
    __syncthreads();
    if (t < 32) {
        float ps = (t < OUT_CH) ? sz[t] * aS2[t] : 0.f;
        float pd = (t < OUT_CH) ? sz[t] * aD2[t] : 0.f;
        #pragma unroll
        for (int o = 16; o > 0; o >>= 1) {
            ps += __shfl_down_sync(0xffffffffu, ps, o);
            pd += __shfl_down_sync(0xffffffffu, pd, o);
        }
        if (t == 0) { g_alS2[n] = ps; g_alD2[n] = pd; }
    }
}

__global__ void k_edge2_p(const int* __restrict__ ei) {
    int e = blockIdx.x * blockDim.x + threadIdx.x;
    if (e >= ET) return;
    int src, dst; edge_endpoints(e, ei, src, dst);
    float v = g_alS2[src] + g_alD2[dst];
    v = v > 0.f ? v : NEG_SLOPE * v;
    float p = __expf(v);
    g_e2[e] = p;
    atomicAdd(&g_den2[dst], p);
}

__global__ void k_edge2_agg(const int* __restrict__ ei) {
    int gw = (blockIdx.x * blockDim.x + threadIdx.x) >> 5;
    int lane = threadIdx.x & 31;
    if (gw >= ET) return;
    int src, dst; edge_endpoints(gw, ei, src, dst);
    float alpha = g_e2[gw] / g_den2[dst];
    if (lane < OUT_CH)
        atomicAdd(&g_agg2[dst * OUT_CH + lane], alpha * g_zpre[src * OUT_CH + lane]);
}

// ---------------- fused: z = agg2 + b2 (-> outZ) ; x_hat = z @ Wd + bd ----------------
__global__ void k_decoder(const float* __restrict__ b2, const float* __restrict__ Wd,
                          const float* __restrict__ bd,
                          float* __restrict__ out, float* __restrict__ outZ) {
    __shared__ float sz[OUT_CH];
    int n = blockIdx.x, t = threadIdx.x;  // 128 threads
    if (t < OUT_CH) {
        float zv = g_agg2[n * OUT_CH + t] + b2[t];
        sz[t] = zv;
        outZ[n * OUT_CH + t] = zv;
    }
    __syncthreads();
    float4 acc = *(const float4*)&bd[t * 4];
    #pragma unroll
    for (int k = 0; k < OUT_CH; k++) {
        float zv = sz[k];
        float4 w = *(const float4*)&Wd[k * IN_CH + t * 4];
        acc.x = fmaf(zv, w.x, acc.x);
        acc.y = fmaf(zv, w.y, acc.y);
        acc.z = fmaf(zv, w.z, acc.z);
        acc.w = fmaf(zv, w.w, acc.w);
    }
    *(float4*)&out[(size_t)n * IN_CH + t * 4] = acc;
}

extern "C" void kernel_launch(void* const* d_in, const int* in_sizes, int n_in,
                              void* d_out, int out_size) {
    const float* x   = (const float*)d_in[0];
    const int*   ei  = (const int*)d_in[1];
    const float* W1  = (const float*)d_in[2];
    const float* aS1 = (const float*)d_in[3];
    const float* aD1 = (const float*)d_in[4];
    const float* b1  = (const float*)d_in[5];
    const float* W2  = (const float*)d_in[6];
    const float* aS2 = (const float*)d_in[7];
    const float* aD2 = (const float*)d_in[8];
    const float* b2  = (const float*)d_in[9];
    const float* Wd  = (const float*)d_in[10];
    const float* bd  = (const float*)d_in[11];
    (void)in_sizes; (void)n_in; (void)out_size;

    float* out  = (float*)d_out;
    float* outZ = out + (size_t)N_NODES * IN_CH;

    k_init<<<(N_NODES * F1 + 255) / 256, 256>>>();

    {
        float* C; cudaGetSymbolAddress((void**)&C, g_h1);
        dim3 grid(F1 / BN, (N_NODES + BM - 1) / BM);
        k_sgemm<<<grid, 256>>>(x, W1, C, N_NODES, F1, IN_CH);
    }

    k_logits1<<<N_NODES, 128>>>(aS1, aD1);

    int eb = (ET + 255) / 256;
    k_edge1_p<<<eb, 256>>>(ei);
    k_edge1_agg<<<(ET * 32 + 255) / 256, 256>>>(ei);

    k_elu<<<(N_NODES * F1 + 255) / 256, 256>>>(b1);

    k_gemm2<<<N_NODES, 128>>>(W2, aS2, aD2);

    k_edge2_p<<<eb, 256>>>(ei);
    k_edge2_agg<<<(ET * 32 + 255) / 256, 256>>>(ei);

    k_decoder<<<N_NODES, 128>>>(b2, Wd, bd, out, outZ);
}

// round 3
// speedup vs baseline: 1.1738x; 1.0881x over previous
#include <cuda_runtime.h>
#include <cuda_bf16.h>
#include <float.h>

#define N_NODES 20000
#define N_EDGES 320000
#define ET      340000
#define IN_CH   512
#define HID     128
#define HEADS   4
#define F1      512
#define OUT_CH  30
#define NEG_SLOPE 0.2f

__device__ float g_h1[N_NODES * F1];
__device__ float g_agg1[N_NODES * F1];          // post ELU(h_agg + b1)
__device__ float g_alS1[N_NODES * HEADS];
__device__ float g_alD1[N_NODES * HEADS];
__device__ float g_zpre[N_NODES * OUT_CH];
__device__ float g_alS2[N_NODES];
__device__ float g_alD2[N_NODES];
__device__ int   g_rowptr[N_NODES + 1];
__device__ int   g_cursor[N_NODES];
__device__ int   g_csr_src[ET];

__device__ __forceinline__ void edge_endpoints(int e, const int* __restrict__ ei,
                                               int& src, int& dst) {
    if (e < N_EDGES) { src = ei[e]; dst = ei[N_EDGES + e]; }
    else { src = e - N_EDGES; dst = src; }
}

__device__ __forceinline__ void ffma2(unsigned long long& acc,
                                      unsigned long long a, unsigned long long b) {
    asm("fma.rn.f32x2 %0, %1, %2, %0;" : "+l"(acc) : "l"(a), "l"(b));
}
__device__ __forceinline__ void upk2(unsigned long long v, float& lo, float& hi) {
    asm("mov.b64 {%0, %1}, %2;" : "=f"(lo), "=f"(hi) : "l"(v));
}

// ================= CSR build =================
__global__ void k_zero_rowptr() {
    int i = blockIdx.x * blockDim.x + threadIdx.x;
    if (i <= N_NODES) g_rowptr[i] = 0;
}
__global__ void k_count(const int* __restrict__ ei) {
    int e = blockIdx.x * blockDim.x + threadIdx.x;
    if (e >= ET) return;
    int src, dst; edge_endpoints(e, ei, src, dst);
    (void)src;
    atomicAdd(&g_rowptr[dst + 1], 1);
}
__global__ void k_scan() {   // single block, 1024 threads; inclusive scan of rowptr
    __shared__ int s[1024];
    __shared__ int carry;
    int tid = threadIdx.x;
    if (tid == 0) carry = 0;
    __syncthreads();
    for (int base = 0; base <= N_NODES; base += 1024) {
        int i = base + tid;
        int v = (i <= N_NODES) ? g_rowptr[i] : 0;
        s[tid] = v;
        __syncthreads();
        #pragma unroll
        for (int off = 1; off < 1024; off <<= 1) {
            int t = (tid >= off) ? s[tid - off] : 0;
            __syncthreads();
            s[tid] += t;
            __syncthreads();
        }
        int out = s[tid] + carry;
        if (i <= N_NODES) {
            g_rowptr[i] = out;
            if (i < N_NODES) g_cursor[i] = out;
        }
        __syncthreads();
        if (tid == 1023) carry = out;
        __syncthreads();
    }
}
__global__ void k_scatter(const int* __restrict__ ei) {
    int e = blockIdx.x * blockDim.x + threadIdx.x;
    if (e >= ET) return;
    int src, dst; edge_endpoints(e, ei, src, dst);
    int pos = atomicAdd(&g_cursor[dst], 1);
    g_csr_src[pos] = src;
}

// ================= GEMM: C = A[M,K] @ B[K,N], k-paired FFMA2 =================
#define BM 128
#define BN 64
#define BK 16
__global__ __launch_bounds__(256, 2)
void k_sgemm(const float* __restrict__ A, const float* __restrict__ B,
             float* __restrict__ C, int M, int N, int K) {
    __shared__ unsigned long long As2[BK / 2][BM];   // (k_even,k_odd) per row
    __shared__ unsigned long long Bs2[BK / 2][BN];   // (k_even,k_odd) per col
    const int tid = threadIdx.x;
    const int tr = tid >> 4;      // 0..15, 8 rows each
    const int tc = tid & 15;      // 0..15, 4 cols each
    const int rowBase = blockIdx.y * BM;
    const int colBase = blockIdx.x * BN;

    unsigned long long acc[8][4];
    #pragma unroll
    for (int i = 0; i < 8; i++)
        #pragma unroll
        for (int j = 0; j < 4; j++) acc[i][j] = 0ull;

    for (int k0 = 0; k0 < K; k0 += BK) {
        // A tile: 128x16 floats; each thread 2 float4 (4 consecutive k)
        #pragma unroll
        for (int t = 0; t < 2; t++) {
            int i = tid * 2 + t;
            int r = i >> 2;
            int c = (i & 3) * 4;
            int gr = rowBase + r;
            float4 v = make_float4(0.f, 0.f, 0.f, 0.f);
            if (gr < M) v = *(const float4*)&A[(size_t)gr * K + k0 + c];
            *reinterpret_cast<float2*>(&As2[(c >> 1)][r])     = make_float2(v.x, v.y);
            *reinterpret_cast<float2*>(&As2[(c >> 1) + 1][r]) = make_float2(v.z, v.w);
        }
        // B tile: 16x64 floats; each thread 1 float4 (one k row, 4 cols)
        {
            int k = tid >> 4;
            int c = (tid & 15) * 4;
            float4 v = *(const float4*)&B[(size_t)(k0 + k) * N + colBase + c];
            float* bs = reinterpret_cast<float*>(&Bs2[k >> 1][0]);
            int half = k & 1;
            bs[(c + 0) * 2 + half] = v.x;
            bs[(c + 1) * 2 + half] = v.y;
            bs[(c + 2) * 2 + half] = v.z;
            bs[(c + 3) * 2 + half] = v.w;
        }
        __syncthreads();
        #pragma unroll
        for (int k2 = 0; k2 < BK / 2; k2++) {
            unsigned long long ap[8], bp[4];
            #pragma unroll
            for (int i2 = 0; i2 < 4; i2++) {
                ulonglong2 a = *reinterpret_cast<const ulonglong2*>(&As2[k2][tr * 8 + i2 * 2]);
                ap[i2 * 2] = a.x; ap[i2 * 2 + 1] = a.y;
            }
            {
                ulonglong2 b0 = *reinterpret_cast<const ulonglong2*>(&Bs2[k2][tc * 4]);
                ulonglong2 b1 = *reinterpret_cast<const ulonglong2*>(&Bs2[k2][tc * 4 + 2]);
                bp[0] = b0.x; bp[1] = b0.y; bp[2] = b1.x; bp[3] = b1.y;
            }
            #pragma unroll
            for (int i = 0; i < 8; i++)
                #pragma unroll
                for (int j = 0; j < 4; j++) ffma2(acc[i][j], ap[i], bp[j]);
        }
        __syncthreads();
    }
    #pragma unroll
    for (int i = 0; i < 8; i++) {
        int gr = rowBase + tr * 8 + i;
        if (gr >= M) continue;
        float o[4];
        #pragma unroll
        for (int j = 0; j < 4; j++) {
            float lo, hi; upk2(acc[i][j], lo, hi);
            o[j] = lo + hi;
        }
        *(float4*)&C[(size_t)gr * N + colBase + tc * 4] = *(float4*)&o[0];
    }
}

// ================= layer 1 attention logits per node =================
__global__ void k_logits1(const float* __restrict__ aS, const float* __restrict__ aD) {
    int n = blockIdx.x;
    int w = threadIdx.x >> 5, lane = threadIdx.x & 31;
    const float* hr = g_h1 + (size_t)n * F1 + w * HID;
    const float* av = aS + w * HID;
    const float* dv = aD + w * HID;
    float s = 0.f, d = 0.f;
    #pragma unroll
    for (int i = 0; i < 4; i++) {
        float hv = hr[lane + i * 32];
        s = fmaf(hv, av[lane + i * 32], s);
        d = fmaf(hv, dv[lane + i * 32], d);
    }
    #pragma unroll
    for (int o = 16; o > 0; o >>= 1) {
        s += __shfl_down_sync(0xffffffffu, s, o);
        d += __shfl_down_sync(0xffffffffu, d, o);
    }
    if (lane == 0) { g_alS1[n * HEADS + w] = s; g_alD1[n * HEADS + w] = d; }
}

// ================= layer 1 fused softmax + aggregate + bias + ELU =================
__global__ __launch_bounds__(256)
void k_agg1(const float* __restrict__ b1) {
    int warp = (blockIdx.x * blockDim.x + threadIdx.x) >> 5;
    int lane = threadIdx.x & 31;
    if (warp >= N_NODES) return;
    int n = warp;
    int beg = g_rowptr[n], end = g_rowptr[n + 1];
    float4 ad = *(const float4*)&g_alD1[n * 4];

    // pass 1: denominators
    float4 den = make_float4(0.f, 0.f, 0.f, 0.f);
    for (int e = beg + lane; e < end; e += 32) {
        int src = g_csr_src[e];
        float4 s = *(const float4*)&g_alS1[src * 4];
        float v;
        v = s.x + ad.x; den.x += __expf(v > 0.f ? v : NEG_SLOPE * v);
        v = s.y + ad.y; den.y += __expf(v > 0.f ? v : NEG_SLOPE * v);
        v = s.z + ad.z; den.z += __expf(v > 0.f ? v : NEG_SLOPE * v);
        v = s.w + ad.w; den.w += __expf(v > 0.f ? v : NEG_SLOPE * v);
    }
    #pragma unroll
    for (int o = 16; o > 0; o >>= 1) {
        den.x += __shfl_xor_sync(0xffffffffu, den.x, o);
        den.y += __shfl_xor_sync(0xffffffffu, den.y, o);
        den.z += __shfl_xor_sync(0xffffffffu, den.z, o);
        den.w += __shfl_xor_sync(0xffffffffu, den.w, o);
    }
    float r0 = 1.f / den.x, r1 = 1.f / den.y, r2 = 1.f / den.z, r3 = 1.f / den.w;

    // pass 2: weighted aggregation (each lane owns 4 channels per head)
    float4 a0 = make_float4(0.f, 0.f, 0.f, 0.f);
    float4 a1 = a0, a2 = a0, a3 = a0;
    for (int e = beg; e < end; e++) {
        int src = g_csr_src[e];
        float4 s = *(const float4*)&g_alS1[src * 4];
        float v, w0, w1, w2, w3;
        v = s.x + ad.x; w0 = __expf(v > 0.f ? v : NEG_SLOPE * v) * r0;
        v = s.y + ad.y; w1 = __expf(v > 0.f ? v : NEG_SLOPE * v) * r1;
        v = s.z + ad.z; w2 = __expf(v > 0.f ? v : NEG_SLOPE * v) * r2;
        v = s.w + ad.w; w3 = __expf(v > 0.f ? v : NEG_SLOPE * v) * r3;
        const float4* hp = (const float4*)&g_h1[(size_t)src * F1];
        float4 h;
        h = hp[lane];      a0.x = fmaf(w0, h.x, a0.x); a0.y = fmaf(w0, h.y, a0.y); a0.z = fmaf(w0, h.z, a0.z); a0.w = fmaf(w0, h.w, a0.w);
        h = hp[32 + lane]; a1.x = fmaf(w1, h.x, a1.x); a1.y = fmaf(w1, h.y, a1.y); a1.z = fmaf(w1, h.z, a1.z); a1.w = fmaf(w1, h.w, a1.w);
        h = hp[64 + lane]; a2.x = fmaf(w2, h.x, a2.x); a2.y = fmaf(w2, h.y, a2.y); a2.z = fmaf(w2, h.z, a2.z); a2.w = fmaf(w2, h.w, a2.w);
        h = hp[96 + lane]; a3.x = fmaf(w3, h.x, a3.x); a3.y = fmaf(w3, h.y, a3.y); a3.z = fmaf(w3, h.z, a3.z); a3.w = fmaf(w3, h.w, a3.w);
    }
    // bias + ELU + store
    float* outp = &g_agg1[(size_t)n * F1];
    float4 acc[4] = { a0, a1, a2, a3 };
    #pragma unroll
    for (int h = 0; h < 4; h++) {
        float4 bb = *(const float4*)&b1[h * HID + lane * 4];
        float4 v = acc[h];
        v.x += bb.x; v.y += bb.y; v.z += bb.z; v.w += bb.w;
        v.x = v.x > 0.f ? v.x : expm1f(v.x);
        v.y = v.y > 0.f ? v.y : expm1f(v.y);
        v.z = v.z > 0.f ? v.z : expm1f(v.z);
        v.w = v.w > 0.f ? v.w : expm1f(v.w);
        *(float4*)&outp[h * HID + lane * 4] = v;
    }
}

// ================= layer 2: z_pre = h2 @ W2 (split-K), logits2 =================
__global__ __launch_bounds__(128)
void k_gemm2(const float* __restrict__ W2,
             const float* __restrict__ aS2, const float* __restrict__ aD2) {
    __shared__ float sh[F1];
    __shared__ float part[4][32];
    int n = blockIdx.x, t = threadIdx.x;
    int w = t >> 5, lane = t & 31;
    *(float4*)&sh[t * 4] = *(const float4*)&g_agg1[(size_t)n * F1 + t * 4];
    __syncthreads();
    float acc = 0.f;
    if (lane < OUT_CH) {
        const float* wp = W2 + (size_t)(w * 128) * OUT_CH + lane;
        const float* sp = sh + w * 128;
        #pragma unroll 8
        for (int k = 0; k < 128; k++) acc = fmaf(sp[k], wp[k * OUT_CH], acc);
    }
    part[w][lane] = acc;
    __syncthreads();
    if (t < 32) {
        float z = part[0][t] + part[1][t] + part[2][t] + part[3][t];
        if (t < OUT_CH) g_zpre[n * OUT_CH + t] = z;
        float ps = (t < OUT_CH) ? z * aS2[t] : 0.f;
        float pd = (t < OUT_CH) ? z * aD2[t] : 0.f;
        #pragma unroll
        for (int o = 16; o > 0; o >>= 1) {
            ps += __shfl_down_sync(0xffffffffu, ps, o);
            pd += __shfl_down_sync(0xffffffffu, pd, o);
        }
        if (t == 0) { g_alS2[n] = ps; g_alD2[n] = pd; }
    }
}

// ================= layer 2 fused softmax + aggregate + bias -> outZ =================
__global__ __launch_bounds__(256)
void k_agg2(const float* __restrict__ b2, float* __restrict__ outZ) {
    int warp = (blockIdx.x * blockDim.x + threadIdx.x) >> 5;
    int lane = threadIdx.x & 31;
    if (warp >= N_NODES) return;
    int n = warp;
    int beg = g_rowptr[n], end = g_rowptr[n + 1];
    float ad = g_alD2[n];

    float den = 0.f;
    for (int e = beg + lane; e < end; e += 32) {
        int src = g_csr_src[e];
        float v = g_alS2[src] + ad;
        den += __expf(v > 0.f ? v : NEG_SLOPE * v);
    }
    #pragma unroll
    for (int o = 16; o > 0; o >>= 1) den += __shfl_xor_sync(0xffffffffu, den, o);
    float rden = 1.f / den;

    float acc = 0.f;
    for (int e = beg; e < end; e++) {
        int src = g_csr_src[e];
        float v = g_alS2[src] + ad;
        float alpha = __expf(v > 0.f ? v : NEG_SLOPE * v) * rden;
        if (lane < OUT_CH) acc = fmaf(alpha, g_zpre[src * OUT_CH + lane], acc);
    }
    if (lane < OUT_CH) outZ[n * OUT_CH + lane] = acc + b2[lane];
}

// ================= decoder: x_hat = z @ Wd + bd =================
__global__ __launch_bounds__(128)
void k_decoder(const float* __restrict__ Wd, const float* __restrict__ bd,
               float* __restrict__ out, const float* __restrict__ z) {
    __shared__ float sz[OUT_CH];
    int n = blockIdx.x, t = threadIdx.x;
    if (t < OUT_CH) sz[t] = z[n * OUT_CH + t];
    __syncthreads();
    float4 acc = *(const float4*)&bd[t * 4];
    #pragma unroll
    for (int k = 0; k < OUT_CH; k++) {
        float zv = sz[k];
        float4 w = *(const float4*)&Wd[k * IN_CH + t * 4];
        acc.x = fmaf(zv, w.x, acc.x);
        acc.y = fmaf(zv, w.y, acc.y);
        acc.z = fmaf(zv, w.z, acc.z);
        acc.w = fmaf(zv, w.w, acc.w);
    }
    *(float4*)&out[(size_t)n * IN_CH + t * 4] = acc;
}

extern "C" void kernel_launch(void* const* d_in, const int* in_sizes, int n_in,
                              void* d_out, int out_size) {
    const float* x   = (const float*)d_in[0];
    const int*   ei  = (const int*)d_in[1];
    const float* W1  = (const float*)d_in[2];
    const float* aS1 = (const float*)d_in[3];
    const float* aD1 = (const float*)d_in[4];
    const float* b1  = (const float*)d_in[5];
    const float* W2  = (const float*)d_in[6];
    const float* aS2 = (const float*)d_in[7];
    const float* aD2 = (const float*)d_in[8];
    const float* b2  = (const float*)d_in[9];
    const float* Wd  = (const float*)d_in[10];
    const float* bd  = (const float*)d_in[11];
    (void)in_sizes; (void)n_in; (void)out_size;

    float* out  = (float*)d_out;
    float* outZ = out + (size_t)N_NODES * IN_CH;

    // CSR build
    k_zero_rowptr<<<(N_NODES + 1 + 255) / 256, 256>>>();
    k_count<<<(ET + 255) / 256, 256>>>(ei);
    k_scan<<<1, 1024>>>();
    k_scatter<<<(ET + 255) / 256, 256>>>(ei);

    // GEMM1: g_h1 = x @ W1
    {
        float* C; cudaGetSymbolAddress((void**)&C, g_h1);
        dim3 grid(F1 / BN, (N_NODES + BM - 1) / BM);
        k_sgemm<<<grid, 256>>>(x, W1, C, N_NODES, F1, IN_CH);
    }

    k_logits1<<<N_NODES, 128>>>(aS1, aD1);
    k_agg1<<<(N_NODES * 32 + 255) / 256, 256>>>(b1);
    k_gemm2<<<N_NODES, 128>>>(W2, aS2, aD2);
    k_agg2<<<(N_NODES * 32 + 255) / 256, 256>>>(b2, outZ);
    k_decoder<<<N_NODES, 128>>>(Wd, bd, out, outZ);
}

// round 4
// speedup vs baseline: 1.2106x; 1.0314x over previous
#include <cuda_runtime.h>
#include <cuda_bf16.h>
#include <float.h>

#define N_NODES 20000
#define N_EDGES 320000
#define ET      340000
#define IN_CH   512
#define HID     128
#define HEADS   4
#define F1      512
#define OUT_CH  30
#define NEG_SLOPE 0.2f

__device__ float g_h1[N_NODES * F1];
__device__ float g_agg1[N_NODES * F1];
__device__ float g_alS1[N_NODES * HEADS];
__device__ float g_alD1[N_NODES * HEADS];
__device__ float g_zpre[N_NODES * OUT_CH];
__device__ float g_alS2[N_NODES];
__device__ float g_alD2[N_NODES];
__device__ int   g_rowptr[N_NODES + 1];
__device__ int   g_cursor[N_NODES];
__device__ int   g_csr_src[ET];

__device__ __forceinline__ void edge_endpoints(int e, const int* __restrict__ ei,
                                               int& src, int& dst) {
    if (e < N_EDGES) { src = ei[e]; dst = ei[N_EDGES + e]; }
    else { src = e - N_EDGES; dst = src; }
}

__device__ __forceinline__ void ffma2(unsigned long long& acc,
                                      unsigned long long a, unsigned long long b) {
    asm("fma.rn.f32x2 %0, %1, %2, %0;" : "+l"(acc) : "l"(a), "l"(b));
}
__device__ __forceinline__ void upk2(unsigned long long v, float& lo, float& hi) {
    asm("mov.b64 {%0, %1}, %2;" : "=f"(lo), "=f"(hi) : "l"(v));
}

// ================= CSR build =================
__global__ void k_zero_rowptr() {
    int i = blockIdx.x * blockDim.x + threadIdx.x;
    if (i <= N_NODES) g_rowptr[i] = 0;
}
__global__ void k_count(const int* __restrict__ ei) {
    int e = blockIdx.x * blockDim.x + threadIdx.x;
    if (e >= ET) return;
    int src, dst; edge_endpoints(e, ei, src, dst);
    (void)src;
    atomicAdd(&g_rowptr[dst + 1], 1);
}
__global__ void k_scan() {
    __shared__ int s[1024];
    __shared__ int carry;
    int tid = threadIdx.x;
    if (tid == 0) carry = 0;
    __syncthreads();
    for (int base = 0; base <= N_NODES; base += 1024) {
        int i = base + tid;
        int v = (i <= N_NODES) ? g_rowptr[i] : 0;
        s[tid] = v;
        __syncthreads();
        #pragma unroll
        for (int off = 1; off < 1024; off <<= 1) {
            int t = (tid >= off) ? s[tid - off] : 0;
            __syncthreads();
            s[tid] += t;
            __syncthreads();
        }
        int out = s[tid] + carry;
        if (i <= N_NODES) {
            g_rowptr[i] = out;
            if (i < N_NODES) g_cursor[i] = out;
        }
        __syncthreads();
        if (tid == 1023) carry = out;
        __syncthreads();
    }
}
__global__ void k_scatter(const int* __restrict__ ei) {
    int e = blockIdx.x * blockDim.x + threadIdx.x;
    if (e >= ET) return;
    int src, dst; edge_endpoints(e, ei, src, dst);
    int pos = atomicAdd(&g_cursor[dst], 1);
    g_csr_src[pos] = src;
}

// ================= GEMM1: C = A[M,K] @ B[K,N], k-paired FFMA2 =================
#define BM 128
#define BN 64
#define BK 16
__global__ __launch_bounds__(256, 2)
void k_sgemm(const float* __restrict__ A, const float* __restrict__ B,
             float* __restrict__ C, int M, int N, int K) {
    __shared__ unsigned long long As2[BK / 2][BM];
    __shared__ unsigned long long Bs2[BK / 2][BN];
    const int tid = threadIdx.x;
    const int tr = tid >> 4;
    const int tc = tid & 15;
    const int rowBase = blockIdx.y * BM;
    const int colBase = blockIdx.x * BN;

    unsigned long long acc[8][4];
    #pragma unroll
    for (int i = 0; i < 8; i++)
        #pragma unroll
        for (int j = 0; j < 4; j++) acc[i][j] = 0ull;

    for (int k0 = 0; k0 < K; k0 += BK) {
        #pragma unroll
        for (int t = 0; t < 2; t++) {
            int i = tid * 2 + t;
            int r = i >> 2;
            int c = (i & 3) * 4;
            int gr = rowBase + r;
            float4 v = make_float4(0.f, 0.f, 0.f, 0.f);
            if (gr < M) v = *(const float4*)&A[(size_t)gr * K + k0 + c];
            *reinterpret_cast<float2*>(&As2[(c >> 1)][r])     = make_float2(v.x, v.y);
            *reinterpret_cast<float2*>(&As2[(c >> 1) + 1][r]) = make_float2(v.z, v.w);
        }
        {
            int k = tid >> 4;
            int c = (tid & 15) * 4;
            float4 v = *(const float4*)&B[(size_t)(k0 + k) * N + colBase + c];
            float* bs = reinterpret_cast<float*>(&Bs2[k >> 1][0]);
            int half = k & 1;
            bs[(c + 0) * 2 + half] = v.x;
            bs[(c + 1) * 2 + half] = v.y;
            bs[(c + 2) * 2 + half] = v.z;
            bs[(c + 3) * 2 + half] = v.w;
        }
        __syncthreads();
        #pragma unroll
        for (int k2 = 0; k2 < BK / 2; k2++) {
            unsigned long long ap[8], bp[4];
            #pragma unroll
            for (int i2 = 0; i2 < 4; i2++) {
                ulonglong2 a = *reinterpret_cast<const ulonglong2*>(&As2[k2][tr * 8 + i2 * 2]);
                ap[i2 * 2] = a.x; ap[i2 * 2 + 1] = a.y;
            }
            {
                ulonglong2 b0 = *reinterpret_cast<const ulonglong2*>(&Bs2[k2][tc * 4]);
                ulonglong2 b1 = *reinterpret_cast<const ulonglong2*>(&Bs2[k2][tc * 4 + 2]);
                bp[0] = b0.x; bp[1] = b0.y; bp[2] = b1.x; bp[3] = b1.y;
            }
            #pragma unroll
            for (int i = 0; i < 8; i++)
                #pragma unroll
                for (int j = 0; j < 4; j++) ffma2(acc[i][j], ap[i], bp[j]);
        }
        __syncthreads();
    }
    #pragma unroll
    for (int i = 0; i < 8; i++) {
        int gr = rowBase + tr * 8 + i;
        if (gr >= M) continue;
        float o[4];
        #pragma unroll
        for (int j = 0; j < 4; j++) {
            float lo, hi; upk2(acc[i][j], lo, hi);
            o[j] = lo + hi;
        }
        *(float4*)&C[(size_t)gr * N + colBase + tc * 4] = *(float4*)&o[0];
    }
}

// ================= layer 1 attention logits per node =================
__global__ void k_logits1(const float* __restrict__ aS, const float* __restrict__ aD) {
    int n = blockIdx.x;
    int w = threadIdx.x >> 5, lane = threadIdx.x & 31;
    const float* hr = g_h1 + (size_t)n * F1 + w * HID;
    const float* av = aS + w * HID;
    const float* dv = aD + w * HID;
    float s = 0.f, d = 0.f;
    #pragma unroll
    for (int i = 0; i < 4; i++) {
        float hv = hr[lane + i * 32];
        s = fmaf(hv, av[lane + i * 32], s);
        d = fmaf(hv, dv[lane + i * 32], d);
    }
    #pragma unroll
    for (int o = 16; o > 0; o >>= 1) {
        s += __shfl_down_sync(0xffffffffu, s, o);
        d += __shfl_down_sync(0xffffffffu, d, o);
    }
    if (lane == 0) { g_alS1[n * HEADS + w] = s; g_alD1[n * HEADS + w] = d; }
}

// ================= layer 1 fused softmax + aggregate + bias + ELU =================
__global__ __launch_bounds__(256)
void k_agg1(const float* __restrict__ b1) {
    int warp = (blockIdx.x * blockDim.x + threadIdx.x) >> 5;
    int lane = threadIdx.x & 31;
    if (warp >= N_NODES) return;
    int n = warp;
    int beg = g_rowptr[n], end = g_rowptr[n + 1];
    float4 ad = *(const float4*)&g_alD1[n * 4];

    float4 den = make_float4(0.f, 0.f, 0.f, 0.f);
    for (int e = beg + lane; e < end; e += 32) {
        int src = g_csr_src[e];
        float4 s = *(const float4*)&g_alS1[src * 4];
        float v;
        v = s.x + ad.x; den.x += __expf(v > 0.f ? v : NEG_SLOPE * v);
        v = s.y + ad.y; den.y += __expf(v > 0.f ? v : NEG_SLOPE * v);
        v = s.z + ad.z; den.z += __expf(v > 0.f ? v : NEG_SLOPE * v);
        v = s.w + ad.w; den.w += __expf(v > 0.f ? v : NEG_SLOPE * v);
    }
    #pragma unroll
    for (int o = 16; o > 0; o >>= 1) {
        den.x += __shfl_xor_sync(0xffffffffu, den.x, o);
        den.y += __shfl_xor_sync(0xffffffffu, den.y, o);
        den.z += __shfl_xor_sync(0xffffffffu, den.z, o);
        den.w += __shfl_xor_sync(0xffffffffu, den.w, o);
    }
    float r0 = 1.f / den.x, r1 = 1.f / den.y, r2 = 1.f / den.z, r3 = 1.f / den.w;

    float4 a0 = make_float4(0.f, 0.f, 0.f, 0.f);
    float4 a1 = a0, a2 = a0, a3 = a0;
    for (int e = beg; e < end; e++) {
        int src = g_csr_src[e];
        float4 s = *(const float4*)&g_alS1[src * 4];
        float v, w0, w1, w2, w3;
        v = s.x + ad.x; w0 = __expf(v > 0.f ? v : NEG_SLOPE * v) * r0;
        v = s.y + ad.y; w1 = __expf(v > 0.f ? v : NEG_SLOPE * v) * r1;
        v = s.z + ad.z; w2 = __expf(v > 0.f ? v : NEG_SLOPE * v) * r2;
        v = s.w + ad.w; w3 = __expf(v > 0.f ? v : NEG_SLOPE * v) * r3;
        const float4* hp = (const float4*)&g_h1[(size_t)src * F1];
        float4 h;
        h = hp[lane];      a0.x = fmaf(w0, h.x, a0.x); a0.y = fmaf(w0, h.y, a0.y); a0.z = fmaf(w0, h.z, a0.z); a0.w = fmaf(w0, h.w, a0.w);
        h = hp[32 + lane]; a1.x = fmaf(w1, h.x, a1.x); a1.y = fmaf(w1, h.y, a1.y); a1.z = fmaf(w1, h.z, a1.z); a1.w = fmaf(w1, h.w, a1.w);
        h = hp[64 + lane]; a2.x = fmaf(w2, h.x, a2.x); a2.y = fmaf(w2, h.y, a2.y); a2.z = fmaf(w2, h.z, a2.z); a2.w = fmaf(w2, h.w, a2.w);
        h = hp[96 + lane]; a3.x = fmaf(w3, h.x, a3.x); a3.y = fmaf(w3, h.y, a3.y); a3.z = fmaf(w3, h.z, a3.z); a3.w = fmaf(w3, h.w, a3.w);
    }
    float* outp = &g_agg1[(size_t)n * F1];
    float4 acc[4] = { a0, a1, a2, a3 };
    #pragma unroll
    for (int h = 0; h < 4; h++) {
        float4 bb = *(const float4*)&b1[h * HID + lane * 4];
        float4 v = acc[h];
        v.x += bb.x; v.y += bb.y; v.z += bb.z; v.w += bb.w;
        v.x = v.x > 0.f ? v.x : expm1f(v.x);
        v.y = v.y > 0.f ? v.y : expm1f(v.y);
        v.z = v.z > 0.f ? v.z : expm1f(v.z);
        v.w = v.w > 0.f ? v.w : expm1f(v.w);
        *(float4*)&outp[h * HID + lane * 4] = v;
    }
}

// ================= gemm2 tiled: g_zpre = g_agg1[M,512] @ W2[512,30] =================
__global__ __launch_bounds__(256, 2)
void k_gemm2t(const float* __restrict__ W2) {
    __shared__ unsigned long long As2[BK / 2][BM];
    __shared__ unsigned long long Bs2[BK / 2][32];
    const int tid = threadIdx.x;
    const int tr = tid >> 4;
    const int tc = tid & 15;
    const int rowBase = blockIdx.x * BM;

    unsigned long long acc[8][2];
    #pragma unroll
    for (int i = 0; i < 8; i++) { acc[i][0] = 0ull; acc[i][1] = 0ull; }

    for (int k0 = 0; k0 < F1; k0 += BK) {
        #pragma unroll
        for (int t = 0; t < 2; t++) {
            int i = tid * 2 + t;
            int r = i >> 2;
            int c = (i & 3) * 4;
            int gr = rowBase + r;
            float4 v = make_float4(0.f, 0.f, 0.f, 0.f);
            if (gr < N_NODES) v = *(const float4*)&g_agg1[(size_t)gr * F1 + k0 + c];
            *reinterpret_cast<float2*>(&As2[(c >> 1)][r])     = make_float2(v.x, v.y);
            *reinterpret_cast<float2*>(&As2[(c >> 1) + 1][r]) = make_float2(v.z, v.w);
        }
        {   // B tile: 16 x 30 (pad to 32) scalar loads, 2 per thread
            #pragma unroll
            for (int t = 0; t < 2; t++) {
                int idx = tid * 2 + t;       // 0..511
                int k = idx >> 5;            // 0..15
                int c = idx & 31;            // 0..31
                float v = (c < OUT_CH) ? W2[(size_t)(k0 + k) * OUT_CH + c] : 0.f;
                float* bs = reinterpret_cast<float*>(&Bs2[k >> 1][0]);
                bs[c * 2 + (k & 1)] = v;
            }
        }
        __syncthreads();
        #pragma unroll
        for (int k2 = 0; k2 < BK / 2; k2++) {
            unsigned long long ap[8], bp[2];
            #pragma unroll
            for (int i2 = 0; i2 < 4; i2++) {
                ulonglong2 a = *reinterpret_cast<const ulonglong2*>(&As2[k2][tr * 8 + i2 * 2]);
                ap[i2 * 2] = a.x; ap[i2 * 2 + 1] = a.y;
            }
            {
                ulonglong2 b = *reinterpret_cast<const ulonglong2*>(&Bs2[k2][tc * 2]);
                bp[0] = b.x; bp[1] = b.y;
            }
            #pragma unroll
            for (int i = 0; i < 8; i++) {
                ffma2(acc[i][0], ap[i], bp[0]);
                ffma2(acc[i][1], ap[i], bp[1]);
            }
        }
        __syncthreads();
    }
    #pragma unroll
    for (int i = 0; i < 8; i++) {
        int gr = rowBase + tr * 8 + i;
        if (gr >= N_NODES) continue;
        #pragma unroll
        for (int j = 0; j < 2; j++) {
            int c = tc * 2 + j;
            if (c < OUT_CH) {
                float lo, hi; upk2(acc[i][j], lo, hi);
                g_zpre[(size_t)gr * OUT_CH + c] = lo + hi;
            }
        }
    }
}

// ================= logits2: warp per node =================
__global__ __launch_bounds__(256)
void k_logits2(const float* __restrict__ aS2, const float* __restrict__ aD2) {
    int warp = (blockIdx.x * blockDim.x + threadIdx.x) >> 5;
    int lane = threadIdx.x & 31;
    if (warp >= N_NODES) return;
    float z = (lane < OUT_CH) ? g_zpre[warp * OUT_CH + lane] : 0.f;
    float ps = (lane < OUT_CH) ? z * aS2[lane] : 0.f;
    float pd = (lane < OUT_CH) ? z * aD2[lane] : 0.f;
    #pragma unroll
    for (int o = 16; o > 0; o >>= 1) {
        ps += __shfl_down_sync(0xffffffffu, ps, o);
        pd += __shfl_down_sync(0xffffffffu, pd, o);
    }
    if (lane == 0) { g_alS2[warp] = ps; g_alD2[warp] = pd; }
}

// ================= layer 2 fused softmax + aggregate + bias -> outZ =================
__global__ __launch_bounds__(256)
void k_agg2(const float* __restrict__ b2, float* __restrict__ outZ) {
    int warp = (blockIdx.x * blockDim.x + threadIdx.x) >> 5;
    int lane = threadIdx.x & 31;
    if (warp >= N_NODES) return;
    int n = warp;
    int beg = g_rowptr[n], end = g_rowptr[n + 1];
    float ad = g_alD2[n];

    float den = 0.f;
    for (int e = beg + lane; e < end; e += 32) {
        int src = g_csr_src[e];
        float v = g_alS2[src] + ad;
        den += __expf(v > 0.f ? v : NEG_SLOPE * v);
    }
    #pragma unroll
    for (int o = 16; o > 0; o >>= 1) den += __shfl_xor_sync(0xffffffffu, den, o);
    float rden = 1.f / den;

    float acc = 0.f;
    for (int e = beg; e < end; e++) {
        int src = g_csr_src[e];
        float v = g_alS2[src] + ad;
        float alpha = __expf(v > 0.f ? v : NEG_SLOPE * v) * rden;
        if (lane < OUT_CH) acc = fmaf(alpha, g_zpre[src * OUT_CH + lane], acc);
    }
    if (lane < OUT_CH) outZ[n * OUT_CH + lane] = acc + b2[lane];
}

// ================= decoder tiled: out = z[M,30] @ Wd[30,512] + bd =================
#define DBN 64
__global__ __launch_bounds__(256, 2)
void k_decodert(const float* __restrict__ Wd, const float* __restrict__ bd,
                float* __restrict__ out, const float* __restrict__ z) {
    __shared__ float As[32][BM + 4];   // z transposed, k-major, pad k 30..31 = 0
    __shared__ float Bs[32][DBN];
    const int tid = threadIdx.x;
    const int tr = tid >> 4;           // 8 rows each
    const int tc = tid & 15;           // 4 cols each
    const int rowBase = blockIdx.y * BM;
    const int colBase = blockIdx.x * DBN;

    // load z tile: 128 rows x 30 cols -> As[k][row]; also zero pad rows/k
    for (int idx = tid; idx < BM * 32; idx += 256) {
        int r = idx >> 5;          // 0..127
        int k = idx & 31;          // 0..31
        int gr = rowBase + r;
        float v = 0.f;
        if (k < OUT_CH && gr < N_NODES) v = z[(size_t)gr * OUT_CH + k];
        As[k][r] = v;
    }
    // load Wd tile: 30 x 64 -> Bs[k][c]
    for (int idx = tid; idx < 32 * DBN; idx += 256) {
        int k = idx >> 6;          // 0..31
        int c = idx & 63;
        Bs[k][c] = (k < OUT_CH) ? Wd[(size_t)k * IN_CH + colBase + c] : 0.f;
    }
    __syncthreads();

    float acc[8][4];
    {
        float4 bb = *(const float4*)&bd[colBase + tc * 4];
        #pragma unroll
        for (int i = 0; i < 8; i++) {
            acc[i][0] = bb.x; acc[i][1] = bb.y; acc[i][2] = bb.z; acc[i][3] = bb.w;
        }
    }
    #pragma unroll
    for (int k = 0; k < OUT_CH; k++) {
        float a[8], b[4];
        #pragma unroll
        for (int i = 0; i < 8; i += 4)
            *(float4*)&a[i] = *(const float4*)&As[k][tr * 8 + i];
        *(float4*)&b[0] = *(const float4*)&Bs[k][tc * 4];
        #pragma unroll
        for (int i = 0; i < 8; i++)
            #pragma unroll
            for (int j = 0; j < 4; j++) acc[i][j] = fmaf(a[i], b[j], acc[i][j]);
    }
    #pragma unroll
    for (int i = 0; i < 8; i++) {
        int gr = rowBase + tr * 8 + i;
        if (gr >= N_NODES) continue;
        *(float4*)&out[(size_t)gr * IN_CH + colBase + tc * 4] = *(float4*)&acc[i][0];
    }
}

extern "C" void kernel_launch(void* const* d_in, const int* in_sizes, int n_in,
                              void* d_out, int out_size) {
    const float* x   = (const float*)d_in[0];
    const int*   ei  = (const int*)d_in[1];
    const float* W1  = (const float*)d_in[2];
    const float* aS1 = (const float*)d_in[3];
    const float* aD1 = (const float*)d_in[4];
    const float* b1  = (const float*)d_in[5];
    const float* W2  = (const float*)d_in[6];
    const float* aS2 = (const float*)d_in[7];
    const float* aD2 = (const float*)d_in[8];
    const float* b2  = (const float*)d_in[9];
    const float* Wd  = (const float*)d_in[10];
    const float* bd  = (const float*)d_in[11];
    (void)in_sizes; (void)n_in; (void)out_size;

    float* out  = (float*)d_out;
    float* outZ = out + (size_t)N_NODES * IN_CH;

    k_zero_rowptr<<<(N_NODES + 1 + 255) / 256, 256>>>();
    k_count<<<(ET + 255) / 256, 256>>>(ei);
    k_scan<<<1, 1024>>>();
    k_scatter<<<(ET + 255) / 256, 256>>>(ei);

    {
        float* C; cudaGetSymbolAddress((void**)&C, g_h1);
        dim3 grid(F1 / BN, (N_NODES + BM - 1) / BM);
        k_sgemm<<<grid, 256>>>(x, W1, C, N_NODES, F1, IN_CH);
    }

    k_logits1<<<N_NODES, 128>>>(aS1, aD1);
    k_agg1<<<(N_NODES * 32 + 255) / 256, 256>>>(b1);

    k_gemm2t<<<(N_NODES + BM - 1) / BM, 256>>>(W2);
    k_logits2<<<(N_NODES * 32 + 255) / 256, 256>>>(aS2, aD2);
    k_agg2<<<(N_NODES * 32 + 255) / 256, 256>>>(b2, outZ);

    {
        dim3 grid(IN_CH / DBN, (N_NODES + BM - 1) / BM);
        k_decodert<<<grid, 256>>>(Wd, bd, out, outZ);
    }
}